// round 10
// baseline (speedup 1.0000x reference)
#include <cuda_runtime.h>
#include <cstdint>

#define BATCH 1024
#define NUM_CLS 58

// ---------------- device scratch (no allocations allowed) ----------------
__device__ unsigned g_pw1[9 * 4 * 128];   // packed w1 signs, layout [tap][word][oc]
__device__ unsigned g_pw2[9 * 4 * 128];
__device__ unsigned g_pw3[9 * 4 * 128];
__device__ unsigned g_pw4[4 * 128];       // layout [word][oc]

// ---------------- weight sign packing (warp-ballot, coalesced) ----------------
__global__ void pack_weights_kernel(const float* __restrict__ w1, const float* __restrict__ w2,
                                    const float* __restrict__ w3, const float* __restrict__ w4) {
    int gw   = (blockIdx.x * blockDim.x + threadIdx.x) >> 5;
    int lane = threadIdx.x & 31;
    if (gw >= 2048) return;
    int t  = gw >> 9;
    int r  = gw & 511;
    int oc = r >> 2;
    int wi = r & 3;
    if (t < 3) {
        const float* w = (t == 0) ? w1 : ((t == 1) ? w2 : w3);
        unsigned* pw   = (t == 0) ? g_pw1 : ((t == 1) ? g_pw2 : g_pw3);
        const float* p = w + ((size_t)(oc * 128 + wi * 32 + lane)) * 9;
        float v[9];
#pragma unroll
        for (int k = 0; k < 9; k++) v[k] = p[k];
        unsigned myword = 0;
#pragma unroll
        for (int tap = 0; tap < 9; tap++) {
            unsigned wd = __ballot_sync(0xffffffffu, v[tap] >= 0.0f);
            if (lane == tap) myword = wd;
        }
        if (lane < 9) pw[(lane * 4 + wi) * 128 + oc] = myword;
    } else {
        float v = w4[oc * 128 + wi * 32 + lane];
        unsigned wd = __ballot_sync(0xffffffffu, v >= 0.0f);
        if (lane == 0) g_pw4[wi * 128 + oc] = wd;
    }
}

// ---- phase-0 helper: PIX pooled pixels sharing 12-col row loads ----
// Per-candidate accumulation order is (c asc, ky asc, kx asc) — identical to prior rounds.
template<int PIX>
__device__ __forceinline__ void conv_group(const float* __restrict__ xs, int y0, int x0c,
                                           const float* __restrict__ wr, int cg,
                                           unsigned* __restrict__ a1w, int pbase, int lane) {
    constexpr int NW = (PIX == 4) ? 3 : 2;    // float4 loads per row
    float acc[PIX][4];
#pragma unroll
    for (int pi = 0; pi < PIX; pi++) {
        acc[pi][0] = 0.f; acc[pi][1] = 0.f; acc[pi][2] = 0.f; acc[pi][3] = 0.f;
    }
#pragma unroll
    for (int c = 0; c < 3; c++) {
#pragma unroll
        for (int dy = 0; dy < 4; dy++) {
            float e[NW * 4];
            const float4* r4 = (const float4*)&xs[c * 1024 + (y0 + dy) * 32 + x0c];
#pragma unroll
            for (int j = 0; j < NW; j++) {
                float4 q = r4[j];
                e[j * 4 + 0] = q.x; e[j * 4 + 1] = q.y; e[j * 4 + 2] = q.z; e[j * 4 + 3] = q.w;
            }
#pragma unroll
            for (int kx = 0; kx < 3; kx++) {
                if (dy <= 2) {
                    float w = wr[c * 9 + dy * 3 + kx];
#pragma unroll
                    for (int pi = 0; pi < PIX; pi++) {
                        acc[pi][0] += e[2 * pi + kx] * w;
                        acc[pi][1] += e[2 * pi + 1 + kx] * w;
                    }
                }
                if (dy >= 1) {
                    float w = wr[c * 9 + (dy - 1) * 3 + kx];
#pragma unroll
                    for (int pi = 0; pi < PIX; pi++) {
                        acc[pi][2] += e[2 * pi + kx] * w;
                        acc[pi][3] += e[2 * pi + 1 + kx] * w;
                    }
                }
            }
        }
    }
#pragma unroll
    for (int pi = 0; pi < PIX; pi++) {
        float best = fmaxf(fmaxf(acc[pi][0], acc[pi][1]), fmaxf(acc[pi][2], acc[pi][3]));
        unsigned word = __ballot_sync(0xffffffffu, best >= 0.0f);
        if (lane == 0) a1w[(pbase + pi) * 4 + cg] = word;
    }
}

// ---------------- single merged model kernel: block = image, 896 threads (28 warps) ----------------
// ONE block per SM (72 regs x 896 = 64512 <= 65536): all 28 warps of an SM belong to the same
// barrier-locked block -> no cross-CTA drift; 1024 blocks = 7 clean waves of 148.
// Warp -> (cg = warp&3, stripe ws = warp>>5... ws = warp>>2 in 0..6). Tasks striped by 7.
__global__ __launch_bounds__(896, 1) void model_kernel(const float* __restrict__ x,
                                                       const float* __restrict__ w0,
                                                       const float* __restrict__ w5,
                                                       float* __restrict__ out) {
    __shared__ float xs[3 * 32 * 32];
    __shared__ uint4 a1s[225];
    __shared__ uint4 a2v[36];
    __shared__ uint4 a3v[9];
    __shared__ unsigned s4w[4];
    __shared__ float rs[128];
    __shared__ float lg[NUM_CLS];

    int b    = blockIdx.x;
    int tid  = threadIdx.x;
    int warp = tid >> 5;
    int lane = tid & 31;
    int cg   = warp & 3;        // channel group 0..3
    int ws   = warp >> 2;       // work stripe 0..6
    int oc   = cg * 32 + lane;

    // ---- load image ----
    const float4* xb4 = (const float4*)(x + (size_t)b * 3072);
    float4* xs4 = (float4*)xs;
    for (int i = tid; i < 768; i += 896) xs4[i] = xb4[i];
    __syncthreads();

    // ---- phase 0: conv0 + pool + sign + pack ----
    // 60 tasks = 15 rows x 4 col-groups; task t -> (py = t>>2, g = t&3). Stripe by 7.
    {
        float wr[27];
#pragma unroll
        for (int k = 0; k < 27; k++) wr[k] = w0[oc * 27 + k];

        unsigned* a1w = (unsigned*)a1s;
        for (int t = ws; t < 60; t += 7) {
            int py = t >> 2, g = t & 3;
            int y0 = 2 * py, pb = py * 15;
            if (g < 3) conv_group<4>(xs, y0, 8 * g, wr, cg, a1w, pb + 4 * g, lane);
            else       conv_group<3>(xs, y0, 24,    wr, cg, a1w, pb + 12,    lane);
        }
    }
    __syncthreads();

    // ---- phase 1: binconv1 (3x3, 15x15->13x13) + pool2x2 -> a2v ----
    {
        uint4 wr[9];
#pragma unroll
        for (int tap = 0; tap < 9; tap++) {
            wr[tap].x = g_pw1[(tap * 4 + 0) * 128 + oc];
            wr[tap].y = g_pw1[(tap * 4 + 1) * 128 + oc];
            wr[tap].z = g_pw1[(tap * 4 + 2) * 128 + oc];
            wr[tap].w = g_pw1[(tap * 4 + 3) * 128 + oc];
        }

        for (int p = ws; p < 36; p += 7) {
            int py = p / 6, px = p - py * 6;
            int y0 = 2 * py, x0 = 2 * px;

            int smin = 1 << 30;
#pragma unroll
            for (int cy = 0; cy < 2; cy++)
#pragma unroll
                for (int cx = 0; cx < 2; cx++) {
                    int s = 0;
#pragma unroll
                    for (int ky = 0; ky < 3; ky++)
#pragma unroll
                        for (int kx = 0; kx < 3; kx++) {
                            uint4 xv = a1s[(y0 + cy + ky) * 15 + (x0 + cx + kx)];
                            uint4 wv = wr[ky * 3 + kx];
                            s += __popc(xv.x ^ wv.x) + __popc(xv.y ^ wv.y) +
                                 __popc(xv.z ^ wv.z) + __popc(xv.w ^ wv.w);
                        }
                    smin = min(smin, s);
                }
            // dot = 1152 - 2*smin ; sign bit = (dot >= 0)
            unsigned word = __ballot_sync(0xffffffffu, smin <= 576);
            if (lane == 0) ((unsigned*)a2v)[p * 4 + cg] = word;
        }
    }
    __syncthreads();

    // ---- phase 2: binconv2 (3x3, 6x6->4x4) + pool k2 s1 -> a3v ----
    {
        uint4 wr[9];
#pragma unroll
        for (int tap = 0; tap < 9; tap++) {
            wr[tap].x = g_pw2[(tap * 4 + 0) * 128 + oc];
            wr[tap].y = g_pw2[(tap * 4 + 1) * 128 + oc];
            wr[tap].z = g_pw2[(tap * 4 + 2) * 128 + oc];
            wr[tap].w = g_pw2[(tap * 4 + 3) * 128 + oc];
        }

        for (int p = ws; p < 9; p += 7) {
            int py = p / 3, px = p - py * 3;

            int smin = 1 << 30;
#pragma unroll
            for (int cy = 0; cy < 2; cy++)
#pragma unroll
                for (int cx = 0; cx < 2; cx++) {
                    int s = 0;
#pragma unroll
                    for (int ky = 0; ky < 3; ky++)
#pragma unroll
                        for (int kx = 0; kx < 3; kx++) {
                            uint4 xv = a2v[(py + cy + ky) * 6 + (px + cx + kx)];
                            uint4 wv = wr[ky * 3 + kx];
                            s += __popc(xv.x ^ wv.x) + __popc(xv.y ^ wv.y) +
                                 __popc(xv.z ^ wv.z) + __popc(xv.w ^ wv.w);
                        }
                    smin = min(smin, s);
                }
            unsigned word = __ballot_sync(0xffffffffu, smin <= 576);
            if (lane == 0) ((unsigned*)a3v)[p * 4 + cg] = word;
        }
    }
    __syncthreads();

    // ---- phase 3: head (first 128 threads = output channel) ----
    if (tid < 128) {
        int s = 0;
#pragma unroll
        for (int tap = 0; tap < 9; tap++) {
            uint4 xv = a3v[tap];
            s += __popc(xv.x ^ g_pw3[(tap * 4 + 0) * 128 + tid]);
            s += __popc(xv.y ^ g_pw3[(tap * 4 + 1) * 128 + tid]);
            s += __popc(xv.z ^ g_pw3[(tap * 4 + 2) * 128 + tid]);
            s += __popc(xv.w ^ g_pw3[(tap * 4 + 3) * 128 + tid]);
        }
        unsigned word = __ballot_sync(0xffffffffu, s <= 576);  // sign(1152 - 2s)
        if (lane == 0) s4w[warp] = word;
    }
    __syncthreads();

    if (tid < 128) {
        int t = 0;
#pragma unroll
        for (int wi = 0; wi < 4; wi++) t += __popc(s4w[wi] ^ g_pw4[wi * 128 + tid]);
        rs[tid] = fmaxf((float)(128 - 2 * t), 0.0f);
    }
    __syncthreads();

    // fp32 1x1 conv to NUM_CLS logits
    if (tid < NUM_CLS) {
        float acc = 0.0f;
#pragma unroll 8
        for (int o = 0; o < 128; o++) acc += w5[tid * 128 + o] * rs[o];
        lg[tid] = acc;
    }
    __syncthreads();

    // softmax over NUM_CLS
    if (tid < NUM_CLS) {
        float m = -3.4e38f;
        for (int j = 0; j < NUM_CLS; j++) m = fmaxf(m, lg[j]);
        float den = 0.0f;
        for (int j = 0; j < NUM_CLS; j++) den += expf(lg[j] - m);
        out[(size_t)b * NUM_CLS + tid] = expf(lg[tid] - m) / den;
    }
}

// ---------------- launch ----------------
extern "C" void kernel_launch(void* const* d_in, const int* in_sizes, int n_in,
                              void* d_out, int out_size) {
    const float* x  = (const float*)d_in[0];
    const float* w0 = (const float*)d_in[1];
    const float* w1 = (const float*)d_in[2];
    const float* w2 = (const float*)d_in[3];
    const float* w3 = (const float*)d_in[4];
    const float* w4 = (const float*)d_in[5];
    const float* w5 = (const float*)d_in[6];
    float* out = (float*)d_out;

    pack_weights_kernel<<<256, 256>>>(w1, w2, w3, w4);
    model_kernel<<<BATCH, 896>>>(x, w0, w5, out);
}

// round 11
// speedup vs baseline: 1.4742x; 1.4742x over previous
#include <cuda_runtime.h>
#include <cstdint>

#define BATCH 1024
#define NUM_CLS 58

typedef unsigned long long ull;

// ---------------- device scratch (no allocations allowed) ----------------
__device__ unsigned g_pw1[9 * 4 * 128];   // packed w1 signs, layout [tap][word][oc]
__device__ unsigned g_pw2[9 * 4 * 128];
__device__ unsigned g_pw3[9 * 4 * 128];
__device__ unsigned g_pw4[4 * 128];       // layout [word][oc]

// ---------------- f32x2 helpers (packed dual-fp32, sm_103a FFMA2) ----------------
__device__ __forceinline__ ull pk2(float a, float b) {
    ull r;
    asm("mov.b64 %0, {%1, %2};" : "=l"(r) : "f"(a), "f"(b));
    return r;
}
__device__ __forceinline__ void fma2(ull& d, ull a, ull b) {
    asm("fma.rn.f32x2 %0, %1, %2, %0;" : "+l"(d) : "l"(a), "l"(b));
}
__device__ __forceinline__ float2 upk(ull v) {
    float2 f;
    asm("mov.b64 {%0, %1}, %2;" : "=f"(f.x), "=f"(f.y) : "l"(v));
    return f;
}

// ---------------- weight sign packing (warp-ballot, coalesced) ----------------
__global__ void pack_weights_kernel(const float* __restrict__ w1, const float* __restrict__ w2,
                                    const float* __restrict__ w3, const float* __restrict__ w4) {
    int gw   = (blockIdx.x * blockDim.x + threadIdx.x) >> 5;
    int lane = threadIdx.x & 31;
    if (gw >= 2048) return;
    int t  = gw >> 9;
    int r  = gw & 511;
    int oc = r >> 2;
    int wi = r & 3;
    if (t < 3) {
        const float* w = (t == 0) ? w1 : ((t == 1) ? w2 : w3);
        unsigned* pw   = (t == 0) ? g_pw1 : ((t == 1) ? g_pw2 : g_pw3);
        const float* p = w + ((size_t)(oc * 128 + wi * 32 + lane)) * 9;
        float v[9];
#pragma unroll
        for (int k = 0; k < 9; k++) v[k] = p[k];
        unsigned myword = 0;
#pragma unroll
        for (int tap = 0; tap < 9; tap++) {
            unsigned wd = __ballot_sync(0xffffffffu, v[tap] >= 0.0f);
            if (lane == tap) myword = wd;
        }
        if (lane < 9) pw[(lane * 4 + wi) * 128 + oc] = myword;
    } else {
        float v = w4[oc * 128 + wi * 32 + lane];
        unsigned wd = __ballot_sync(0xffffffffu, v >= 0.0f);
        if (lane == 0) g_pw4[wi * 128 + oc] = wd;
    }
}

// ---- phase-0 helper: PIX pooled pixels sharing 12-col row loads, FFMA2 packed ----
// Candidate pair (cx=0,cx=1) packed into one f32x2 accumulator; per-candidate
// accumulation order is (c asc, ky asc, kx asc) — bit-identical to prior rounds.
template<int PIX>
__device__ __forceinline__ void conv_group(const float* __restrict__ xs, int y0, int x0c,
                                           const float* __restrict__ wr, int cg,
                                           unsigned* __restrict__ a1w, int pbase, int lane) {
    constexpr int NW = (PIX == 4) ? 3 : 2;    // float4 loads per row
    constexpr int NP = 2 * PIX + 1;           // adjacent pairs (e[s],e[s+1]), s=0..NP-1
    ull A0[PIX], A1[PIX];                     // cy=0 / cy=1, each = (cx0,cx1)
#pragma unroll
    for (int pi = 0; pi < PIX; pi++) { A0[pi] = 0ull; A1[pi] = 0ull; }

#pragma unroll
    for (int c = 0; c < 3; c++) {
        ull wp[9];
#pragma unroll
        for (int k = 0; k < 9; k++) { float w = wr[c * 9 + k]; wp[k] = pk2(w, w); }
#pragma unroll
        for (int dy = 0; dy < 4; dy++) {
            float e[NW * 4];
            const float4* r4 = (const float4*)&xs[c * 1024 + (y0 + dy) * 32 + x0c];
#pragma unroll
            for (int j = 0; j < NW; j++) {
                float4 q = r4[j];
                e[j * 4 + 0] = q.x; e[j * 4 + 1] = q.y; e[j * 4 + 2] = q.z; e[j * 4 + 3] = q.w;
            }
            ull pr[NP];
#pragma unroll
            for (int s = 0; s < NP; s++) pr[s] = pk2(e[s], e[s + 1]);
#pragma unroll
            for (int kx = 0; kx < 3; kx++) {
                if (dy <= 2) {
                    ull w = wp[dy * 3 + kx];
#pragma unroll
                    for (int pi = 0; pi < PIX; pi++) fma2(A0[pi], pr[2 * pi + kx], w);
                }
                if (dy >= 1) {
                    ull w = wp[(dy - 1) * 3 + kx];
#pragma unroll
                    for (int pi = 0; pi < PIX; pi++) fma2(A1[pi], pr[2 * pi + kx], w);
                }
            }
        }
    }
#pragma unroll
    for (int pi = 0; pi < PIX; pi++) {
        float2 v0 = upk(A0[pi]);
        float2 v1 = upk(A1[pi]);
        float best = fmaxf(fmaxf(v0.x, v0.y), fmaxf(v1.x, v1.y));
        unsigned word = __ballot_sync(0xffffffffu, best >= 0.0f);
        if (lane == 0) a1w[(pbase + pi) * 4 + cg] = word;
    }
}

// ---------------- single merged model kernel: block = image, 128 threads (4 warps) ----------------
__global__ __launch_bounds__(128, 7) void model_kernel(const float* __restrict__ x,
                                                       const float* __restrict__ w0,
                                                       const float* __restrict__ w5,
                                                       float* __restrict__ out) {
    __shared__ float xs[3 * 32 * 32];
    __shared__ uint4 a1s[225];
    __shared__ uint4 a2v[36];
    __shared__ uint4 a3v[9];
    __shared__ unsigned s4w[4];
    __shared__ float rs[128];
    __shared__ float lg[NUM_CLS];

    int b    = blockIdx.x;
    int tid  = threadIdx.x;
    int warp = tid >> 5;
    int lane = tid & 31;

    // ---- load image ----
    const float4* xb4 = (const float4*)(x + (size_t)b * 3072);
    float4* xs4 = (float4*)xs;
    for (int i = tid; i < 768; i += 128) xs4[i] = xb4[i];
    __syncthreads();

    // ---- phase 0: conv0 + pool + sign + pack (4 warps: cg = warp) ----
    {
        int cg = warp;
        int oc = cg * 32 + lane;

        float wr[27];
#pragma unroll
        for (int k = 0; k < 27; k++) wr[k] = w0[oc * 27 + k];

        unsigned* a1w = (unsigned*)a1s;
        for (int py = 0; py < 15; py++) {
            int y0 = 2 * py;
            int pb = py * 15;
            // groups of pooled pixels: {0-3}, {4-7}, {8-11}, {12-14}
            conv_group<4>(xs, y0, 0,  wr, cg, a1w, pb + 0,  lane);
            conv_group<4>(xs, y0, 8,  wr, cg, a1w, pb + 4,  lane);
            conv_group<4>(xs, y0, 16, wr, cg, a1w, pb + 8,  lane);
            conv_group<3>(xs, y0, 24, wr, cg, a1w, pb + 12, lane);
        }
    }
    __syncthreads();

    // ---- phase 1: binconv1 (4 warps: cg = warp, 36 pixels each) ----
    {
        int cg = warp;
        int oc = cg * 32 + lane;

        uint4 wr[9];
#pragma unroll
        for (int tap = 0; tap < 9; tap++) {
            wr[tap].x = g_pw1[(tap * 4 + 0) * 128 + oc];
            wr[tap].y = g_pw1[(tap * 4 + 1) * 128 + oc];
            wr[tap].z = g_pw1[(tap * 4 + 2) * 128 + oc];
            wr[tap].w = g_pw1[(tap * 4 + 3) * 128 + oc];
        }

        for (int p = 0; p < 36; p++) {
            int py = p / 6, px = p - py * 6;
            int y0 = 2 * py, x0 = 2 * px;

            int smin = 1 << 30;
#pragma unroll
            for (int cy = 0; cy < 2; cy++)
#pragma unroll
                for (int cx = 0; cx < 2; cx++) {
                    int s = 0;
#pragma unroll
                    for (int ky = 0; ky < 3; ky++)
#pragma unroll
                        for (int kx = 0; kx < 3; kx++) {
                            uint4 xv = a1s[(y0 + cy + ky) * 15 + (x0 + cx + kx)];
                            uint4 wv = wr[ky * 3 + kx];
                            s += __popc(xv.x ^ wv.x) + __popc(xv.y ^ wv.y) +
                                 __popc(xv.z ^ wv.z) + __popc(xv.w ^ wv.w);
                        }
                    smin = min(smin, s);
                }
            // dot = 1152 - 2*smin ; sign bit = (dot >= 0)
            unsigned word = __ballot_sync(0xffffffffu, smin <= 576);
            if (lane == 0) ((unsigned*)a2v)[p * 4 + cg] = word;
        }
    }
    __syncthreads();

    // ---- phase 2: binconv2 (4 warps: cg = warp, 9 pixels each) ----
    {
        int cg = warp;
        int oc = cg * 32 + lane;

        uint4 wr[9];
#pragma unroll
        for (int tap = 0; tap < 9; tap++) {
            wr[tap].x = g_pw2[(tap * 4 + 0) * 128 + oc];
            wr[tap].y = g_pw2[(tap * 4 + 1) * 128 + oc];
            wr[tap].z = g_pw2[(tap * 4 + 2) * 128 + oc];
            wr[tap].w = g_pw2[(tap * 4 + 3) * 128 + oc];
        }

        for (int p = 0; p < 9; p++) {
            int py = p / 3, px = p - py * 3;

            int smin = 1 << 30;
#pragma unroll
            for (int cy = 0; cy < 2; cy++)
#pragma unroll
                for (int cx = 0; cx < 2; cx++) {
                    int s = 0;
#pragma unroll
                    for (int ky = 0; ky < 3; ky++)
#pragma unroll
                        for (int kx = 0; kx < 3; kx++) {
                            uint4 xv = a2v[(py + cy + ky) * 6 + (px + cx + kx)];
                            uint4 wv = wr[ky * 3 + kx];
                            s += __popc(xv.x ^ wv.x) + __popc(xv.y ^ wv.y) +
                                 __popc(xv.z ^ wv.z) + __popc(xv.w ^ wv.w);
                        }
                    smin = min(smin, s);
                }
            unsigned word = __ballot_sync(0xffffffffu, smin <= 576);
            if (lane == 0) ((unsigned*)a3v)[p * 4 + cg] = word;
        }
    }
    __syncthreads();

    // ---- phase 3: head (128 threads = output channel) ----
    {
        int s = 0;
#pragma unroll
        for (int tap = 0; tap < 9; tap++) {
            uint4 xv = a3v[tap];
            s += __popc(xv.x ^ g_pw3[(tap * 4 + 0) * 128 + tid]);
            s += __popc(xv.y ^ g_pw3[(tap * 4 + 1) * 128 + tid]);
            s += __popc(xv.z ^ g_pw3[(tap * 4 + 2) * 128 + tid]);
            s += __popc(xv.w ^ g_pw3[(tap * 4 + 3) * 128 + tid]);
        }
        unsigned word = __ballot_sync(0xffffffffu, s <= 576);  // sign(1152 - 2s)
        if (lane == 0) s4w[warp] = word;
    }
    __syncthreads();

    {
        int t = 0;
#pragma unroll
        for (int wi = 0; wi < 4; wi++) t += __popc(s4w[wi] ^ g_pw4[wi * 128 + tid]);
        rs[tid] = fmaxf((float)(128 - 2 * t), 0.0f);
    }
    __syncthreads();

    // fp32 1x1 conv to NUM_CLS logits
    if (tid < NUM_CLS) {
        float acc = 0.0f;
#pragma unroll 8
        for (int o = 0; o < 128; o++) acc += w5[tid * 128 + o] * rs[o];
        lg[tid] = acc;
    }
    __syncthreads();

    // softmax over NUM_CLS
    if (tid < NUM_CLS) {
        float m = -3.4e38f;
        for (int j = 0; j < NUM_CLS; j++) m = fmaxf(m, lg[j]);
        float den = 0.0f;
        for (int j = 0; j < NUM_CLS; j++) den += expf(lg[j] - m);
        out[(size_t)b * NUM_CLS + tid] = expf(lg[tid] - m) / den;
    }
}

// ---------------- launch ----------------
extern "C" void kernel_launch(void* const* d_in, const int* in_sizes, int n_in,
                              void* d_out, int out_size) {
    const float* x  = (const float*)d_in[0];
    const float* w0 = (const float*)d_in[1];
    const float* w1 = (const float*)d_in[2];
    const float* w2 = (const float*)d_in[3];
    const float* w3 = (const float*)d_in[4];
    const float* w4 = (const float*)d_in[5];
    const float* w5 = (const float*)d_in[6];
    float* out = (float*)d_out;

    pack_weights_kernel<<<256, 256>>>(w1, w2, w3, w4);
    model_kernel<<<BATCH, 128>>>(x, w0, w5, out);
}